// round 3
// baseline (speedup 1.0000x reference)
#include <cuda_runtime.h>
#include <cuda_bf16.h>
#include <cstdio>

// Problem constants
#define PB 2
#define PT 2048
#define PC 1024
#define PH 16
#define PD 64
#define PM (PB * PT)          // 4096
#define QKV_N (3 * PH * PD)   // 3072

// Scratch (allocation-free rule: __device__ globals)
__device__ float g_q[PB * PH * PT * PD];
__device__ float g_k[PB * PH * PT * PD];
__device__ float g_v[PB * PH * PT * PD];
__device__ float g_y[PM * PC];

// ---------------------------------------------------------------------------
// Fast exp: FFMA-only (avoid MUFU bottleneck; 67M exps in attention).
// exp(x) = 2^(x*log2e); degree-5 Taylor of 2^f on [0,1), rel err ~8e-5.
// ---------------------------------------------------------------------------
__device__ __forceinline__ float fast_exp(float x) {
    float y = fmaxf(x * 1.4426950408889634f, -126.0f);
    float n = floorf(y);
    float f = y - n;
    float p = 0.0013333558f;
    p = fmaf(p, f, 0.0096181291f);
    p = fmaf(p, f, 0.0555041087f);
    p = fmaf(p, f, 0.2402265069f);
    p = fmaf(p, f, 0.6931471806f);
    p = fmaf(p, f, 1.0f);
    int e = (int)n;
    return p * __int_as_float((e + 127) << 23);
}

// ---------------------------------------------------------------------------
// Kernel 1: fused QKV projection. NT GEMM: out[m,n] = sum_c x[m,c]*W[n,c]
// A = x [4096,1024] row-major (K contig), B = w_{q,k,v} [1024,1024] (K contig).
// Block tile 128x128, K-tile 8, 256 threads, 8x8 per thread.
// Writes q/k/v in [b][h][t][d] layout.
// ---------------------------------------------------------------------------
__global__ __launch_bounds__(256) void qkv_proj_kernel(
    const float* __restrict__ x, const float* __restrict__ wq,
    const float* __restrict__ wk, const float* __restrict__ wv) {
    __shared__ float As[8][128];
    __shared__ float Bs[8][128];

    const int tid = threadIdx.x;
    const int bm = blockIdx.x * 128;
    const int bn = blockIdx.y * 128;          // 0..3071
    const int which = bn >> 10;               // 0=q,1=k,2=v (128 | 1024)
    const int nbase = bn & 1023;
    const float* w = (which == 0) ? wq : (which == 1) ? wk : wv;
    float* outp = (which == 0) ? g_q : (which == 1) ? g_k : g_v;

    const int l_row = tid >> 1;               // 0..127
    const int l_k = (tid & 1) << 2;           // 0 or 4
    const int tx = tid & 15;
    const int ty = tid >> 4;

    float acc[8][8];
#pragma unroll
    for (int i = 0; i < 8; i++)
#pragma unroll
        for (int j = 0; j < 8; j++) acc[i][j] = 0.f;

    const float* aptr = x + (size_t)(bm + l_row) * PC + l_k;
    const float* bptr = w + (size_t)(nbase + l_row) * PC + l_k;

    for (int k0 = 0; k0 < PC; k0 += 8) {
        float4 av = *(const float4*)(aptr + k0);
        float4 bv = *(const float4*)(bptr + k0);
        As[l_k + 0][l_row] = av.x; As[l_k + 1][l_row] = av.y;
        As[l_k + 2][l_row] = av.z; As[l_k + 3][l_row] = av.w;
        Bs[l_k + 0][l_row] = bv.x; Bs[l_k + 1][l_row] = bv.y;
        Bs[l_k + 2][l_row] = bv.z; Bs[l_k + 3][l_row] = bv.w;
        __syncthreads();
#pragma unroll
        for (int kk = 0; kk < 8; kk++) {
            float a[8], b[8];
            *(float4*)&a[0] = *(const float4*)&As[kk][ty * 8];
            *(float4*)&a[4] = *(const float4*)&As[kk][ty * 8 + 4];
            *(float4*)&b[0] = *(const float4*)&Bs[kk][tx * 8];
            *(float4*)&b[4] = *(const float4*)&Bs[kk][tx * 8 + 4];
#pragma unroll
            for (int i = 0; i < 8; i++)
#pragma unroll
                for (int j = 0; j < 8; j++) acc[i][j] = fmaf(a[i], b[j], acc[i][j]);
        }
        __syncthreads();
    }

    // scatter into [b][h][t][d]
#pragma unroll
    for (int i = 0; i < 8; i++) {
        int m = bm + ty * 8 + i;
        int b = m >> 11;        // /2048
        int t = m & 2047;
#pragma unroll
        for (int j = 0; j < 8; j++) {
            int n = nbase + tx * 8 + j;
            int h = n >> 6;
            int d = n & 63;
            outp[((size_t)((b << 4) + h) * PT + t) * PD + d] = acc[i][j];
        }
    }
}

// ---------------------------------------------------------------------------
// Kernel 2: causal flash attention, fp32.
// Block = 256 threads, 64-query tile per block, 64-key tiles.
// Smem: Qs[d][q], KP[d][kcol] (reused as P^T[kcol][q]), Vs[k][d], pitch 68.
// Online softmax state m/l per row, shfl reductions (4 threads per row).
// ---------------------------------------------------------------------------
#define APITCH 68
#define ATTN_SMEM_BYTES ((3 * 64 * APITCH + 3 * 64) * 4)

__global__ __launch_bounds__(256) void attn_kernel() {
    extern __shared__ float smem_raw[];
    float (*Qs)[APITCH] = (float(*)[APITCH])smem_raw;
    float (*KP)[APITCH] = (float(*)[APITCH])(smem_raw + 64 * APITCH);
    float (*Vs)[APITCH] = (float(*)[APITCH])(smem_raw + 2 * 64 * APITCH);
    float* m_s = smem_raw + 3 * 64 * APITCH;
    float* l_s = m_s + 64;
    float* corr_s = l_s + 64;

    const int tid = threadIdx.x;
    const int tx = tid & 15, ty = tid >> 4;
    const int bh = blockIdx.y;                 // b*16 + h
    const int q0 = blockIdx.x << 6;
    const size_t base = (size_t)bh * PT * PD;
    const float* qg = g_q + base;
    const float* kg = g_k + base;
    const float* vg = g_v + base;

    // Load Q tile transposed: Qs[d][q]
    {
        int r = tid >> 2;
        int dbase = (tid & 3) << 4;
        const float* row = qg + (size_t)(q0 + r) * PD + dbase;
#pragma unroll
        for (int i = 0; i < 16; i += 4) {
            float4 v = *(const float4*)(row + i);
            Qs[dbase + i + 0][r] = v.x;
            Qs[dbase + i + 1][r] = v.y;
            Qs[dbase + i + 2][r] = v.z;
            Qs[dbase + i + 3][r] = v.w;
        }
    }
    if (tid < 64) { m_s[tid] = -1e30f; l_s[tid] = 0.f; }

    float o[4][4];
#pragma unroll
    for (int i = 0; i < 4; i++)
#pragma unroll
        for (int j = 0; j < 4; j++) o[i][j] = 0.f;

    const int jmax = q0 >> 6;
    for (int jt = 0; jt <= jmax; jt++) {
        const int k0 = jt << 6;
        // Load K transposed (KP[d][kcol]) and V natural (Vs[k][d])
        {
            int r = tid >> 2;
            int dbase = (tid & 3) << 4;
            const float* krow = kg + (size_t)(k0 + r) * PD + dbase;
            const float* vrow = vg + (size_t)(k0 + r) * PD + dbase;
#pragma unroll
            for (int i = 0; i < 16; i += 4) {
                float4 kv = *(const float4*)(krow + i);
                KP[dbase + i + 0][r] = kv.x;
                KP[dbase + i + 1][r] = kv.y;
                KP[dbase + i + 2][r] = kv.z;
                KP[dbase + i + 3][r] = kv.w;
                *(float4*)&Vs[r][dbase + i] = *(const float4*)(vrow + i);
            }
        }
        __syncthreads();

        // S = Q K^T : thread computes 4x4 (q rows ty*4.., k cols tx*4..)
        float s[4][4];
#pragma unroll
        for (int i = 0; i < 4; i++)
#pragma unroll
            for (int j = 0; j < 4; j++) s[i][j] = 0.f;
#pragma unroll 16
        for (int d = 0; d < 64; d++) {
            const float4 aq = *(const float4*)&Qs[d][ty << 2];
            const float4 bk = *(const float4*)&KP[d][tx << 2];
            const float av[4] = {aq.x, aq.y, aq.z, aq.w};
            const float bv[4] = {bk.x, bk.y, bk.z, bk.w};
#pragma unroll
            for (int i = 0; i < 4; i++)
#pragma unroll
                for (int j = 0; j < 4; j++) s[i][j] = fmaf(av[i], bv[j], s[i][j]);
        }
        __syncthreads();  // everyone done reading KP before it becomes P^T

        // scale + causal mask, store transposed: KP[kcol][qrow]
        const float scale = 0.125f;  // 1/sqrt(64)
#pragma unroll
        for (int i = 0; i < 4; i++) {
            int qi = q0 + (ty << 2) + i;
#pragma unroll
            for (int j = 0; j < 4; j++) {
                int ki = k0 + (tx << 2) + j;
                float v = s[i][j] * scale;
                if (ki > qi) v = -1e30f;
                KP[(tx << 2) + j][(ty << 2) + i] = v;
            }
        }
        __syncthreads();

        // Online softmax: 4 threads per row, shfl-reduce max & sum
        {
            int r = tid >> 2, p = tid & 3;
            int cbase = p << 4;
            float tmax = -1e30f;
#pragma unroll
            for (int c = 0; c < 16; c++) tmax = fmaxf(tmax, KP[cbase + c][r]);
            tmax = fmaxf(tmax, __shfl_xor_sync(0xffffffffu, tmax, 1));
            tmax = fmaxf(tmax, __shfl_xor_sync(0xffffffffu, tmax, 2));
            float mold = m_s[r];
            float newm = fmaxf(mold, tmax);
            float psum = 0.f;
#pragma unroll
            for (int c = 0; c < 16; c++) {
                float pv = fast_exp(KP[cbase + c][r] - newm);
                KP[cbase + c][r] = pv;
                psum += pv;
            }
            psum += __shfl_xor_sync(0xffffffffu, psum, 1);
            psum += __shfl_xor_sync(0xffffffffu, psum, 2);
            if (p == 0) {
                float cr = fast_exp(mold - newm);
                corr_s[r] = cr;
                l_s[r] = l_s[r] * cr + psum;
                m_s[r] = newm;
            }
        }
        __syncthreads();

        // O = O*corr + P V
#pragma unroll
        for (int i = 0; i < 4; i++) {
            float cf = corr_s[(ty << 2) + i];
#pragma unroll
            for (int j = 0; j < 4; j++) o[i][j] *= cf;
        }
#pragma unroll 16
        for (int kk = 0; kk < 64; kk++) {
            const float4 ap = *(const float4*)&KP[kk][ty << 2];
            const float4 bp = *(const float4*)&Vs[kk][tx << 2];
            const float av[4] = {ap.x, ap.y, ap.z, ap.w};
            const float bv[4] = {bp.x, bp.y, bp.z, bp.w};
#pragma unroll
            for (int i = 0; i < 4; i++)
#pragma unroll
                for (int j = 0; j < 4; j++) o[i][j] = fmaf(av[i], bv[j], o[i][j]);
        }
        __syncthreads();  // protect KP/Vs for next tile
    }

    // Epilogue: normalize + store y in [b][t][h*64+d]
    const int b = bh >> 4;
    const int h = bh & 15;
#pragma unroll
    for (int i = 0; i < 4; i++) {
        int q = q0 + (ty << 2) + i;
        float inv = 1.f / l_s[(ty << 2) + i];
#pragma unroll
        for (int j = 0; j < 4; j++) {
            int d = (tx << 2) + j;
            g_y[((size_t)b * PT + q) * PC + h * PD + d] = o[i][j] * inv;
        }
    }
}

// ---------------------------------------------------------------------------
// Kernel 3: output projection. NN GEMM: out[m,n] = sum_k y[m,k]*wo[k,n]
// ---------------------------------------------------------------------------
__global__ __launch_bounds__(256) void out_proj_kernel(
    const float* __restrict__ wo, float* __restrict__ out) {
    __shared__ float As[8][128];
    __shared__ float Bs[8][128];

    const int tid = threadIdx.x;
    const int bm = blockIdx.x * 128;
    const int bn = blockIdx.y * 128;
    const int a_row = tid >> 1;
    const int a_k = (tid & 1) << 2;
    const int b_r = tid >> 5;             // 0..7
    const int b_c = (tid & 31) << 2;      // 0..124
    const int tx = tid & 15, ty = tid >> 4;

    float acc[8][8];
#pragma unroll
    for (int i = 0; i < 8; i++)
#pragma unroll
        for (int j = 0; j < 8; j++) acc[i][j] = 0.f;

    const float* aptr = g_y + (size_t)(bm + a_row) * PC + a_k;
    const float* bptr = wo + (size_t)b_r * PC + bn + b_c;

    for (int k0 = 0; k0 < PC; k0 += 8) {
        float4 av = *(const float4*)(aptr + k0);
        As[a_k + 0][a_row] = av.x; As[a_k + 1][a_row] = av.y;
        As[a_k + 2][a_row] = av.z; As[a_k + 3][a_row] = av.w;
        float4 bv = *(const float4*)(bptr + (size_t)k0 * PC);
        *(float4*)&Bs[b_r][b_c] = bv;
        __syncthreads();
#pragma unroll
        for (int kk = 0; kk < 8; kk++) {
            float a[8], b[8];
            *(float4*)&a[0] = *(const float4*)&As[kk][ty * 8];
            *(float4*)&a[4] = *(const float4*)&As[kk][ty * 8 + 4];
            *(float4*)&b[0] = *(const float4*)&Bs[kk][tx * 8];
            *(float4*)&b[4] = *(const float4*)&Bs[kk][tx * 8 + 4];
#pragma unroll
            for (int i = 0; i < 8; i++)
#pragma unroll
                for (int j = 0; j < 8; j++) acc[i][j] = fmaf(a[i], b[j], acc[i][j]);
        }
        __syncthreads();
    }

#pragma unroll
    for (int i = 0; i < 8; i++) {
        int m = bm + ty * 8 + i;
        float* orow = out + (size_t)m * PC + bn + tx * 8;
        *(float4*)&orow[0] = *(float4*)&acc[i][0];
        *(float4*)&orow[4] = *(float4*)&acc[i][4];
    }
}

// ---------------------------------------------------------------------------
extern "C" void kernel_launch(void* const* d_in, const int* in_sizes, int n_in,
                              void* d_out, int out_size) {
    const float* x  = (const float*)d_in[0];
    const float* wq = (const float*)d_in[1];
    const float* wk = (const float*)d_in[2];
    const float* wv = (const float*)d_in[3];
    const float* wo = (const float*)d_in[4];
    float* out = (float*)d_out;

    cudaFuncSetAttribute(attn_kernel,
                         cudaFuncAttributeMaxDynamicSharedMemorySize,
                         ATTN_SMEM_BYTES);

    qkv_proj_kernel<<<dim3(PM / 128, QKV_N / 128), 256>>>(x, wq, wk, wv);
    attn_kernel<<<dim3(PT / 64, PB * PH), 256, ATTN_SMEM_BYTES>>>();
    out_proj_kernel<<<dim3(PM / 128, PC / 128), 256>>>(wo, out);
}